// round 16
// baseline (speedup 1.0000x reference)
#include <cuda_runtime.h>
#include <math.h>

// Problem constants (fixed by reference)
#define BB     32          // batch
#define TT     64          // timesteps
#define DD     512         // d_emb / LSTM units
#define H4     2048        // 4 * units
#define VV     32000       // vocab
#define NCH    19          // LSTM K chunks total (8 emb + 2 content + 1 style + 8 h)
#define NVB    250         // g_acc partial chunks (128 vocab each)
#define NPB    250         // psum partial blocks (128 vocab each)

// Persistent device state / scratch (no allocations allowed)
__device__ __align__(16) float g_hbuf[2][BB*DD];
__device__ __align__(16) float g_cbuf[2][BB*DD];
__device__ __align__(16) float g_hT[DD*BB];          // h in [k][b] layout
__device__ __align__(16) float g_emb[BB*DD];         // current soft embedding
__device__ __align__(16) float g_zpart[NCH][BB][H4]; // LSTM gate partials (8-10 static)
__device__ __align__(16) float g_zl[4][VV*BB];       // logit K-quarter partials
__device__ __align__(16) float g_acc[(size_t)NVB*BB*DD]; // weighted-E partials
__device__ __align__(16) float g_psum[NPB*BB];       // exp partial sums
__device__ int g_cnt[32];                            // fin election counters

// ---------- packed f32x2 helpers ----------
static __device__ __forceinline__ unsigned long long ffma2(unsigned long long a,
                                                           unsigned long long b,
                                                           unsigned long long c) {
    unsigned long long d;
    asm("fma.rn.f32x2 %0, %1, %2, %3;" : "=l"(d) : "l"(a), "l"(b), "l"(c));
    return d;
}
static __device__ __forceinline__ unsigned long long pack2(float x, float y) {
    unsigned long long r;
    asm("mov.b64 %0, {%1, %2};" : "=l"(r) : "f"(x), "f"(y));
    return r;
}
static __device__ __forceinline__ float2 unpack2(unsigned long long v) {
    float2 r;
    asm("mov.b64 {%0, %1}, %2;" : "=f"(r.x), "=f"(r.y) : "l"(v));
    return r;
}
static __device__ __forceinline__ float sigf(float x) { return 1.0f / (1.0f + expf(-x)); }

// ---------- cp.async (LDGSTS) helpers ----------
static __device__ __forceinline__ unsigned sptr(const void* p) {
    return (unsigned)__cvta_generic_to_shared(p);
}
static __device__ __forceinline__ void cp16(unsigned dst, const void* src) {
    asm volatile("cp.async.cg.shared.global [%0], [%1], 16;\n" :: "r"(dst), "l"(src));
}
static __device__ __forceinline__ void cp_commit() {
    asm volatile("cp.async.commit_group;\n" ::: "memory");
}
static __device__ __forceinline__ void cp_wait1() {
    asm volatile("cp.async.wait_group 1;\n" ::: "memory");
}

// ---------- t = 0: SOS embedding, zero state ----------
__global__ void k_init(const float* __restrict__ E, float* __restrict__ out) {
    int b = blockIdx.x, d = threadIdx.x;       // grid 32, block 512
    float e = E[d];                            // E[SOS=0][d]
    g_emb[b*DD + d] = e;
    out[(size_t)(b*TT)*DD + d] = e;
    g_hbuf[0][b*DD + d] = 0.f;
    g_cbuf[0][b*DD + d] = 0.f;
}

// ---------- shared inner op for the LSTM GEMM ----------
static __device__ __forceinline__ void fma4p(unsigned long long (&acc)[4][2],
                                             float x, const float* wb) {
    unsigned long long x2 = pack2(x, x);
    #pragma unroll
    for (int g = 0; g < 4; g++) {
        float4 w = *(const float4*)(wb + g*DD);
        acc[g][0] = ffma2(pack2(w.x, w.y), x2, acc[g][0]);
        acc[g][1] = ffma2(pack2(w.z, w.w), x2, acc[g][1]);
    }
}

// ---------- once-per-call: constant content/style Wk chunks (8,9,10) ----------
// grid (32, 3), block 128
__global__ __launch_bounds__(128) void k_prep(
    const float* __restrict__ content, const float* __restrict__ style,
    const float* __restrict__ Wk)
{
    int tid = threadIdx.x;
    int b  = tid >> 2;
    int jl = tid & 3;
    int j0 = blockIdx.x * 16 + jl * 4;
    int y = blockIdx.y;                // 0,1 -> content halves; 2 -> style
    int ch = 8 + y;

    unsigned long long acc[4][2];
    #pragma unroll
    for (int g = 0; g < 4; g++) { acc[g][0] = 0ULL; acc[g][1] = 0ULL; }

    const float* Wb; const float* xp; int n;
    if (y < 2) { Wb = Wk + (size_t)(512 + y*64)*H4 + j0; xp = content + b*128 + y*64; n = 64; }
    else       { Wb = Wk + (size_t)640*H4 + j0;          xp = style + b*16;           n = 16; }

    #pragma unroll 4
    for (int k = 0; k < n; k++) fma4p(acc, xp[k], Wb + (size_t)k*H4);

    float* zp = &g_zpart[ch][b][0];
    #pragma unroll
    for (int g = 0; g < 4; g++) {
        float2 a = unpack2(acc[g][0]);
        float2 c = unpack2(acc[g][1]);
        *(float4*)(zp + g*DD + j0) = make_float4(a.x, a.y, c.x, c.y);
    }
}

// ---------- LSTM gate GEMM + fused epilogue (last-block election) ----------
// grid (32, 16), block 128: y<8 -> emb chunk y; y>=8 -> h chunk 11+(y-8).
// After writing partials, the last-arriving block per jb reduces all 19 chunks,
// applies gates, and updates h/c state (deterministic: fixed read order).
__global__ __launch_bounds__(128) void k_lstm_mm(
    const float* __restrict__ Wk, const float* __restrict__ Wr,
    const float* __restrict__ bias, int cur)
{
    int tid = threadIdx.x;
    int b  = tid >> 2;                 // 0..31
    int jl = tid & 3;                  // 0..3
    int j0 = blockIdx.x * 16 + jl * 4; // 4 consecutive output units per gate
    int y = blockIdx.y;                // 0..15

    unsigned long long acc[4][2];
    #pragma unroll
    for (int g = 0; g < 4; g++) { acc[g][0] = 0ULL; acc[g][1] = 0ULL; }

    const float* Wb; const float* xp; int ch;
    if (y < 8) { ch = y;        Wb = Wk + (size_t)(y*64)*H4 + j0;     xp = g_emb + b*DD + y*64; }
    else       { ch = 11+(y-8); Wb = Wr + (size_t)((y-8)*64)*H4 + j0; xp = g_hbuf[cur^1] + b*DD + (y-8)*64; }

    #pragma unroll 4
    for (int k = 0; k < 64; k++) fma4p(acc, xp[k], Wb + (size_t)k*H4);

    float* zp = &g_zpart[ch][b][0];
    #pragma unroll
    for (int g = 0; g < 4; g++) {
        float2 a = unpack2(acc[g][0]);
        float2 c = unpack2(acc[g][1]);
        *(float4*)(zp + g*DD + j0) = make_float4(a.x, a.y, c.x, c.y);
    }

    // ---- last-block election for the epilogue ----
    __threadfence();
    __shared__ int elect;
    if (tid == 0) {
        int old = atomicAdd(&g_cnt[blockIdx.x], 1);
        elect = ((old & 15) == 15);
    }
    __syncthreads();
    if (!elect) return;
    __threadfence();                   // acquire: other blocks' partials visible

    // epilogue for columns j0..j0+3 (this thread), all via fixed-order reduction
    float4 z[4];
    #pragma unroll
    for (int g = 0; g < 4; g++) z[g] = *(const float4*)(bias + g*DD + j0);
    #pragma unroll
    for (int c2 = 0; c2 < NCH; c2++) {
        const float* zq = &g_zpart[c2][b][0];
        #pragma unroll
        for (int g = 0; g < 4; g++) {
            float4 p = *(const float4*)(zq + g*DD + j0);
            z[g].x += p.x; z[g].y += p.y; z[g].z += p.z; z[g].w += p.w;
        }
    }
    const float* cprev = g_cbuf[cur ^ 1] + b*DD;
    float* cnew = g_cbuf[cur] + b*DD;
    float* hnew = g_hbuf[cur] + b*DD;
    float hv[4];
    {
        float zi[4] = {z[0].x, z[0].y, z[0].z, z[0].w};
        float zf[4] = {z[1].x, z[1].y, z[1].z, z[1].w};
        float zg[4] = {z[2].x, z[2].y, z[2].z, z[2].w};
        float zo[4] = {z[3].x, z[3].y, z[3].z, z[3].w};
        #pragma unroll
        for (int u = 0; u < 4; u++) {
            int j = j0 + u;
            float iv = sigf(zi[u]), fv = sigf(zf[u]);
            float gv = tanhf(zg[u]), ov = sigf(zo[u]);
            float c = fv * cprev[j] + iv * gv;
            hv[u] = ov * tanhf(c);
            cnew[j] = c;
        }
        #pragma unroll
        for (int u = 0; u < 4; u++) {
            hnew[j0 + u] = hv[u];
            g_hT[(j0 + u)*BB + b] = hv[u];  // k-major for the logits kernel
        }
    }
}

// ---------- partial logits: one K-quarter per block, cp.async lookahead-2 ----------
// grid (250, 4 kq), block 128: tid = cl(0..31) + 32*bq(0..3).
// Thread: cols v..v+3 (v = bx*128 + cl*4), batches bq*8..bq*8+7, K=128 in 16 stages of 8.
__global__ __launch_bounds__(128, 8) void k_zl(const float* __restrict__ Ws)
{
    __shared__ __align__(16) float Hs[128*BB];     // 16KB: one K-quarter of h, [k][b]
    __shared__ __align__(16) float Wt[3][8*128];   // 12KB: Ws stage [kk][v-chunk]
    int tid = threadIdx.x;
    int cl = tid & 31, bq = tid >> 5;
    int kq = blockIdx.y;
    int v0 = blockIdx.x * 128;

    const float* wsrc = Ws + (size_t)(kq*128)*VV + v0;
    int kk0 = tid >> 5;                            // this thread's stage row pair
    int seg = tid & 31;

    // prologue: issue stages 0 and 1
    cp16(sptr(&Wt[0][kk0*128 + seg*4]),       wsrc + (size_t)kk0*VV + seg*4);
    cp16(sptr(&Wt[0][(kk0+4)*128 + seg*4]),   wsrc + (size_t)(kk0+4)*VV + seg*4);
    cp_commit();
    cp16(sptr(&Wt[1][kk0*128 + seg*4]),       wsrc + (size_t)(8 + kk0)*VV + seg*4);
    cp16(sptr(&Wt[1][(kk0+4)*128 + seg*4]),   wsrc + (size_t)(8 + kk0+4)*VV + seg*4);
    cp_commit();

    {   // stage H quarter (rows kq*128 .. +127) with normal loads meanwhile
        const float4* src = (const float4*)g_hT + kq*1024;
        float4* dst = (float4*)Hs;
        #pragma unroll
        for (int i = 0; i < 8; i++) dst[tid + 128*i] = src[tid + 128*i];
    }

    unsigned long long a[4][4];                    // [col][batch-pair]
    #pragma unroll
    for (int c = 0; c < 4; c++)
        #pragma unroll
        for (int i = 0; i < 4; i++) a[c][i] = 0ULL;

    int r_idx = 0, w_idx = 2;                      // rotating buffer indices
    for (int s = 0; s < 16; s++) {
        cp_wait1();                                // stage s landed (s+1 may fly)
        __syncthreads();                           // visible; prior reads of w_idx done
        if (s + 2 < 16) {                          // issue stage s+2
            float* dst = Wt[w_idx];
            cp16(sptr(dst + kk0*128 + seg*4),
                 wsrc + (size_t)((s+2)*8 + kk0)*VV + seg*4);
            cp16(sptr(dst + (kk0+4)*128 + seg*4),
                 wsrc + (size_t)((s+2)*8 + kk0+4)*VV + seg*4);
        }
        cp_commit();

        const float* wbuf = Wt[r_idx];
        #pragma unroll
        for (int kk = 0; kk < 8; kk++) {
            float4 wf = *(const float4*)(wbuf + kk*128 + cl*4);
            unsigned long long w0 = pack2(wf.x, wf.x);
            unsigned long long w1 = pack2(wf.y, wf.y);
            unsigned long long w2 = pack2(wf.z, wf.z);
            unsigned long long w3 = pack2(wf.w, wf.w);
            const ulonglong2* hr = (const ulonglong2*)(Hs + (s*8 + kk)*BB + bq*8);
            ulonglong2 q0 = hr[0], q1 = hr[1];     // broadcast LDS feed 16 FFMA2
            a[0][0]=ffma2(q0.x,w0,a[0][0]); a[0][1]=ffma2(q0.y,w0,a[0][1]);
            a[0][2]=ffma2(q1.x,w0,a[0][2]); a[0][3]=ffma2(q1.y,w0,a[0][3]);
            a[1][0]=ffma2(q0.x,w1,a[1][0]); a[1][1]=ffma2(q0.y,w1,a[1][1]);
            a[1][2]=ffma2(q1.x,w1,a[1][2]); a[1][3]=ffma2(q1.y,w1,a[1][3]);
            a[2][0]=ffma2(q0.x,w2,a[2][0]); a[2][1]=ffma2(q0.y,w2,a[2][1]);
            a[2][2]=ffma2(q1.x,w2,a[2][2]); a[2][3]=ffma2(q1.y,w2,a[2][3]);
            a[3][0]=ffma2(q0.x,w3,a[3][0]); a[3][1]=ffma2(q0.y,w3,a[3][1]);
            a[3][2]=ffma2(q1.x,w3,a[3][2]); a[3][3]=ffma2(q1.y,w3,a[3][3]);
        }
        r_idx = (r_idx == 2) ? 0 : r_idx + 1;
        w_idx = (w_idx == 2) ? 0 : w_idx + 1;
    }

    int v = v0 + cl * 4;
    #pragma unroll
    for (int c = 0; c < 4; c++) {                  // col v+c, batches bq*8..+7
        float2 p0 = unpack2(a[c][0]), p1 = unpack2(a[c][1]);
        float2 p2 = unpack2(a[c][2]), p3 = unpack2(a[c][3]);
        float4* o = (float4*)(g_zl[kq] + (size_t)(v+c)*BB + bq*8);
        o[0] = make_float4(p0.x, p0.y, p1.x, p1.y);
        o[1] = make_float4(p2.x, p2.y, p3.x, p3.y);
    }
}

// ---------- fused exp + partial (exp @ E): grid (250 vchunks, 4 dq), block 128 ----------
__global__ __launch_bounds__(128, 8) void k_emb(const float* __restrict__ E,
                                                const float* __restrict__ bs)
{
    __shared__ __align__(16) float smP[128*BB];    // 16KB: P[128][32]
    __shared__ __align__(16) float Et[3][8*128];   // 12KB: E stage [vv][d-chunk]
    __shared__ float redp[128];
    int tid = threadIdx.x;
    int v0 = blockIdx.x * 128;
    int d0 = blockIdx.y * 128;

    const float* esrc = E + (size_t)v0*DD + d0;
    int kk0 = tid >> 5;
    int seg = tid & 31;

    // prologue: issue E stages 0 and 1 (fly during the exp front)
    cp16(sptr(&Et[0][kk0*128 + seg*4]),     esrc + (size_t)kk0*DD + seg*4);
    cp16(sptr(&Et[0][(kk0+4)*128 + seg*4]), esrc + (size_t)(kk0+4)*DD + seg*4);
    cp_commit();
    cp16(sptr(&Et[1][kk0*128 + seg*4]),     esrc + (size_t)(8 + kk0)*DD + seg*4);
    cp16(sptr(&Et[1][(kk0+4)*128 + seg*4]), esrc + (size_t)(8 + kk0+4)*DD + seg*4);
    cp_commit();

    // ---- exp front
    {   // thread: rows {rr, rr+32, rr+64, rr+96} (local), batches bqf*8..+7
        int rr = tid >> 2, bqf = tid & 3;
        #pragma unroll
        for (int m = 0; m < 4; m++) {
            int lr = rr + m*32;                    // local row 0..127
            int v = v0 + lr;
            float wv[8];
            #pragma unroll
            for (int j = 0; j < 8; j++) wv[j] = 0.f;
            #pragma unroll
            for (int q = 0; q < 4; q++) {
                const float4* p = (const float4*)(g_zl[q] + (size_t)v*BB + bqf*8);
                float4 x = p[0], y = p[1];
                wv[0]+=x.x; wv[1]+=x.y; wv[2]+=x.z; wv[3]+=x.w;
                wv[4]+=y.x; wv[5]+=y.y; wv[6]+=y.z; wv[7]+=y.w;
            }
            float bv = bs[v];
            float4* sp = (float4*)(smP + lr*BB + bqf*8);
            sp[0] = make_float4(expf(wv[0]+bv), expf(wv[1]+bv),
                                expf(wv[2]+bv), expf(wv[3]+bv));
            sp[1] = make_float4(expf(wv[4]+bv), expf(wv[5]+bv),
                                expf(wv[6]+bv), expf(wv[7]+bv));
        }
    }
    __syncthreads();                               // P tile complete

    if ((int)blockIdx.y == (int)(blockIdx.x & 3)) { // psum once per vchunk, spread over dq
        int b2 = tid & 31, sl = tid >> 5;
        float s = 0.f;
        #pragma unroll 4
        for (int u = sl; u < 128; u += 4) s += smP[u*BB + b2];
        redp[sl*32 + b2] = s;
        __syncthreads();
        if (tid < 32)
            g_psum[blockIdx.x*BB + tid] =
                redp[tid] + redp[32+tid] + redp[64+tid] + redp[96+tid];
    }

    // ---- E GEMM mainloop: tid = cl(0..31) + 32*bq(0..3)
    int cl = tid & 31, bq = tid >> 5;
    unsigned long long a[4][4];                    // [d-col][batch-pair]
    #pragma unroll
    for (int c = 0; c < 4; c++)
        #pragma unroll
        for (int i = 0; i < 4; i++) a[c][i] = 0ULL;

    int r_idx = 0, w_idx = 2;
    for (int s = 0; s < 16; s++) {
        cp_wait1();
        __syncthreads();
        if (s + 2 < 16) {
            float* dst = Et[w_idx];
            cp16(sptr(dst + kk0*128 + seg*4),
                 esrc + (size_t)((s+2)*8 + kk0)*DD + seg*4);
            cp16(sptr(dst + (kk0+4)*128 + seg*4),
                 esrc + (size_t)((s+2)*8 + kk0+4)*DD + seg*4);
        }
        cp_commit();

        const float* ebuf = Et[r_idx];
        #pragma unroll
        for (int kk = 0; kk < 8; kk++) {
            float4 ef = *(const float4*)(ebuf + kk*128 + cl*4);
            unsigned long long e0 = pack2(ef.x, ef.x);
            unsigned long long e1 = pack2(ef.y, ef.y);
            unsigned long long e2 = pack2(ef.z, ef.z);
            unsigned long long e3 = pack2(ef.w, ef.w);
            const ulonglong2* wr = (const ulonglong2*)(smP + (s*8 + kk)*BB + bq*8);
            ulonglong2 q0 = wr[0], q1 = wr[1];
            a[0][0]=ffma2(q0.x,e0,a[0][0]); a[0][1]=ffma2(q0.y,e0,a[0][1]);
            a[0][2]=ffma2(q1.x,e0,a[0][2]); a[0][3]=ffma2(q1.y,e0,a[0][3]);
            a[1][0]=ffma2(q0.x,e1,a[1][0]); a[1][1]=ffma2(q0.y,e1,a[1][1]);
            a[1][2]=ffma2(q1.x,e1,a[1][2]); a[1][3]=ffma2(q1.y,e1,a[1][3]);
            a[2][0]=ffma2(q0.x,e2,a[2][0]); a[2][1]=ffma2(q0.y,e2,a[2][1]);
            a[2][2]=ffma2(q1.x,e2,a[2][2]); a[2][3]=ffma2(q1.y,e2,a[2][3]);
            a[3][0]=ffma2(q0.x,e3,a[3][0]); a[3][1]=ffma2(q0.y,e3,a[3][1]);
            a[3][2]=ffma2(q1.x,e3,a[3][2]); a[3][3]=ffma2(q1.y,e3,a[3][3]);
        }
        r_idx = (r_idx == 2) ? 0 : r_idx + 1;
        w_idx = (w_idx == 2) ? 0 : w_idx + 1;
    }

    int d = d0 + cl * 4;
    int pc = blockIdx.x;                   // 0..249 partial chunk
    float* ob = g_acc + ((size_t)pc*BB)*DD + d;
    #pragma unroll
    for (int i = 0; i < 4; i++) {          // rows bq*8+2i, bq*8+2i+1
        float2 t0 = unpack2(a[0][i]), t1 = unpack2(a[1][i]);
        float2 t2 = unpack2(a[2][i]), t3 = unpack2(a[3][i]);
        *(float4*)(ob + (size_t)(bq*8 + 2*i    )*DD) = make_float4(t0.x, t1.x, t2.x, t3.x);
        *(float4*)(ob + (size_t)(bq*8 + 2*i + 1)*DD) = make_float4(t0.y, t1.y, t2.y, t3.y);
    }
}

// ---------- final reduce: normalize soft embedding, write output ----------
// grid (32 b, 8 dgroups), block 256 (8 slices x 32 float2 lanes)
__global__ __launch_bounds__(256) void k_reduce(float* __restrict__ out, int t) {
    __shared__ float2 red[8][32];
    __shared__ float s_inv;
    int b = blockIdx.x, dg = blockIdx.y;
    int tid = threadIdx.x;
    int s = tid >> 5, d2l = tid & 31;

    float2 a = make_float2(0.f, 0.f);
    const float2* gin = (const float2*)g_acc;
    for (int c = s; c < NVB; c += 8) {
        float2 p = gin[((size_t)c*BB + b)*(DD/2) + dg*32 + d2l];
        a.x += p.x; a.y += p.y;
    }
    red[s][d2l] = a;

    if (tid < 32) {                        // deterministic softmax denominator
        float ts = 0.f;
        for (int c = tid; c < NPB; c += 32) ts += g_psum[c*BB + b];
        #pragma unroll
        for (int o = 16; o > 0; o >>= 1) ts += __shfl_xor_sync(0xffffffffu, ts, o);
        if (tid == 0) s_inv = 1.0f / ts;
    }
    __syncthreads();

    if (s == 0) {
        #pragma unroll
        for (int i = 1; i < 8; i++) { a.x += red[i][d2l].x; a.y += red[i][d2l].y; }
        float inv = s_inv;
        a.x *= inv; a.y *= inv;
        int d2 = dg*32 + d2l;
        ((float2*)g_emb)[b*(DD/2) + d2] = a;
        ((float2*)out)[((size_t)b*TT + t)*(DD/2) + d2] = a;
    }
}

extern "C" void kernel_launch(void* const* d_in, const int* in_sizes, int n_in,
                              void* d_out, int out_size) {
    const float* content = (const float*)d_in[0];
    const float* style   = (const float*)d_in[1];
    const float* E       = (const float*)d_in[2];
    const float* Wk      = (const float*)d_in[3];
    const float* Wr      = (const float*)d_in[4];
    const float* bias    = (const float*)d_in[5];
    const float* Ws      = (const float*)d_in[6];
    const float* bs      = (const float*)d_in[7];
    float* out = (float*)d_out;

    k_init<<<BB, DD>>>(E, out);
    k_prep<<<dim3(32, 3), 128>>>(content, style, Wk);   // constant Wk chunks, once
    for (int t = 1; t < TT; t++) {
        int cur = t & 1;
        k_lstm_mm<<<dim3(32, 16), 128>>>(Wk, Wr, bias, cur);  // fused epilogue
        k_zl<<<dim3(250, 4), 128>>>(Ws);
        k_emb<<<dim3(250, 4), 128>>>(E, bs);
        k_reduce<<<dim3(BB, 8), 256>>>(out, t);
    }
}

// round 17
// speedup vs baseline: 1.1616x; 1.1616x over previous
#include <cuda_runtime.h>
#include <math.h>

// Problem constants (fixed by reference)
#define BB     32          // batch
#define TT     64          // timesteps
#define DD     512         // d_emb / LSTM units
#define H4     2048        // 4 * units
#define VV     32000       // vocab
#define NCH    19          // LSTM K chunks total (8 emb + 2 content + 1 style + 8 h)
#define NVB    250         // g_acc partial chunks (128 vocab each)
#define NPB    250         // psum partial blocks (128 vocab each)

// Persistent device state / scratch (no allocations allowed)
__device__ __align__(16) float g_hbuf[2][BB*DD];
__device__ __align__(16) float g_cbuf[2][BB*DD];
__device__ __align__(16) float g_hT[DD*BB];          // h in [k][b] layout
__device__ __align__(16) float g_emb[BB*DD];         // current soft embedding
__device__ __align__(16) float g_zpart[NCH][BB][H4]; // LSTM gate partials (8-10 static)
__device__ __align__(16) float g_zl[4][VV*BB];       // logit K-quarter partials
__device__ __align__(16) float g_acc[(size_t)NVB*BB*DD]; // weighted-E partials
__device__ __align__(16) float g_psum[NPB*BB];       // exp partial sums

// ---------- packed f32x2 helpers ----------
static __device__ __forceinline__ unsigned long long ffma2(unsigned long long a,
                                                           unsigned long long b,
                                                           unsigned long long c) {
    unsigned long long d;
    asm("fma.rn.f32x2 %0, %1, %2, %3;" : "=l"(d) : "l"(a), "l"(b), "l"(c));
    return d;
}
static __device__ __forceinline__ unsigned long long pack2(float x, float y) {
    unsigned long long r;
    asm("mov.b64 %0, {%1, %2};" : "=l"(r) : "f"(x), "f"(y));
    return r;
}
static __device__ __forceinline__ float2 unpack2(unsigned long long v) {
    float2 r;
    asm("mov.b64 {%0, %1}, %2;" : "=f"(r.x), "=f"(r.y) : "l"(v));
    return r;
}
static __device__ __forceinline__ float sigf(float x) { return 1.0f / (1.0f + expf(-x)); }

// ---------- cp.async (LDGSTS) helpers ----------
static __device__ __forceinline__ unsigned sptr(const void* p) {
    return (unsigned)__cvta_generic_to_shared(p);
}
static __device__ __forceinline__ void cp16(unsigned dst, const void* src) {
    asm volatile("cp.async.cg.shared.global [%0], [%1], 16;\n" :: "r"(dst), "l"(src));
}
static __device__ __forceinline__ void cp_commit() {
    asm volatile("cp.async.commit_group;\n" ::: "memory");
}
static __device__ __forceinline__ void cp_wait1() {
    asm volatile("cp.async.wait_group 1;\n" ::: "memory");
}

// ---------- t = 0: SOS embedding, zero state ----------
__global__ void k_init(const float* __restrict__ E, float* __restrict__ out) {
    int b = blockIdx.x, d = threadIdx.x;       // grid 32, block 512
    float e = E[d];                            // E[SOS=0][d]
    g_emb[b*DD + d] = e;
    out[(size_t)(b*TT)*DD + d] = e;
    g_hbuf[0][b*DD + d] = 0.f;
    g_cbuf[0][b*DD + d] = 0.f;
}

// ---------- shared inner op for the LSTM GEMM ----------
static __device__ __forceinline__ void fma4p(unsigned long long (&acc)[4][2],
                                             float x, const float* wb) {
    unsigned long long x2 = pack2(x, x);
    #pragma unroll
    for (int g = 0; g < 4; g++) {
        float4 w = *(const float4*)(wb + g*DD);
        acc[g][0] = ffma2(pack2(w.x, w.y), x2, acc[g][0]);
        acc[g][1] = ffma2(pack2(w.z, w.w), x2, acc[g][1]);
    }
}

// ---------- once-per-call: constant content/style Wk chunks (8,9,10) ----------
// grid (32, 3), block 128
__global__ __launch_bounds__(128) void k_prep(
    const float* __restrict__ content, const float* __restrict__ style,
    const float* __restrict__ Wk)
{
    int tid = threadIdx.x;
    int b  = tid >> 2;
    int jl = tid & 3;
    int j0 = blockIdx.x * 16 + jl * 4;
    int y = blockIdx.y;                // 0,1 -> content halves; 2 -> style
    int ch = 8 + y;

    unsigned long long acc[4][2];
    #pragma unroll
    for (int g = 0; g < 4; g++) { acc[g][0] = 0ULL; acc[g][1] = 0ULL; }

    const float* Wb; const float* xp; int n;
    if (y < 2) { Wb = Wk + (size_t)(512 + y*64)*H4 + j0; xp = content + b*128 + y*64; n = 64; }
    else       { Wb = Wk + (size_t)640*H4 + j0;          xp = style + b*16;           n = 16; }

    #pragma unroll 4
    for (int k = 0; k < n; k++) fma4p(acc, xp[k], Wb + (size_t)k*H4);

    float* zp = &g_zpart[ch][b][0];
    #pragma unroll
    for (int g = 0; g < 4; g++) {
        float2 a = unpack2(acc[g][0]);
        float2 c = unpack2(acc[g][1]);
        *(float4*)(zp + g*DD + j0) = make_float4(a.x, a.y, c.x, c.y);
    }
}

// ---------- LSTM gate GEMM, dynamic K chunks only (emb + h) ----------
// grid (32, 16), block 128: y<8 -> emb chunk y; y>=8 -> h chunk 11+(y-8)
__global__ __launch_bounds__(128) void k_lstm_mm(
    const float* __restrict__ Wk, const float* __restrict__ Wr, int cur)
{
    int tid = threadIdx.x;
    int b  = tid >> 2;                 // 0..31
    int jl = tid & 3;                  // 0..3
    int j0 = blockIdx.x * 16 + jl * 4; // 4 consecutive output units per gate
    int y = blockIdx.y;                // 0..15

    unsigned long long acc[4][2];
    #pragma unroll
    for (int g = 0; g < 4; g++) { acc[g][0] = 0ULL; acc[g][1] = 0ULL; }

    const float* Wb; const float* xp; int ch;
    if (y < 8) { ch = y;        Wb = Wk + (size_t)(y*64)*H4 + j0;     xp = g_emb + b*DD + y*64; }
    else       { ch = 11+(y-8); Wb = Wr + (size_t)((y-8)*64)*H4 + j0; xp = g_hbuf[cur^1] + b*DD + (y-8)*64; }

    #pragma unroll 4
    for (int k = 0; k < 64; k++) fma4p(acc, xp[k], Wb + (size_t)k*H4);

    float* zp = &g_zpart[ch][b][0];
    #pragma unroll
    for (int g = 0; g < 4; g++) {
        float2 a = unpack2(acc[g][0]);
        float2 c = unpack2(acc[g][1]);
        *(float4*)(zp + g*DD + j0) = make_float4(a.x, a.y, c.x, c.y);
    }
}

// ---------- LSTM epilogue: reduce chunks, gates, state update ----------
__global__ __launch_bounds__(512) void k_lstm_fin(const float* __restrict__ bias, int cur) {
    int b = blockIdx.x, j = threadIdx.x;   // grid 32, block 512
    float z0 = bias[j], z1 = bias[DD + j], z2 = bias[2*DD + j], z3 = bias[3*DD + j];
    #pragma unroll
    for (int ch = 0; ch < NCH; ch++) {
        const float* zp = &g_zpart[ch][b][0];
        z0 += zp[j]; z1 += zp[DD + j]; z2 += zp[2*DD + j]; z3 += zp[3*DD + j];
    }
    float iv = sigf(z0), fv = sigf(z1), gv = tanhf(z2), ov = sigf(z3);
    float c = fv * g_cbuf[cur ^ 1][b*DD + j] + iv * gv;
    float h = ov * tanhf(c);
    g_cbuf[cur][b*DD + j] = c;
    g_hbuf[cur][b*DD + j] = h;
    g_hT[j*BB + b] = h;                    // k-major for the logits kernel
}

// ---------- partial logits: one K-quarter per block, cp.async lookahead-2 ----------
// grid (250, 4 kq), block 128: tid = cl(0..31) + 32*bq(0..3).
// Thread: cols v..v+3 (v = bx*128 + cl*4), batches bq*8..bq*8+7, K=128 in 16 stages of 8.
__global__ __launch_bounds__(128, 8) void k_zl(const float* __restrict__ Ws)
{
    __shared__ __align__(16) float Hs[128*BB];     // 16KB: one K-quarter of h, [k][b]
    __shared__ __align__(16) float Wt[3][8*128];   // 12KB: Ws stage [kk][v-chunk]
    int tid = threadIdx.x;
    int cl = tid & 31, bq = tid >> 5;
    int kq = blockIdx.y;
    int v0 = blockIdx.x * 128;

    const float* wsrc = Ws + (size_t)(kq*128)*VV + v0;
    int kk0 = tid >> 5;                            // this thread's stage row pair
    int seg = tid & 31;

    // prologue: issue stages 0 and 1
    cp16(sptr(&Wt[0][kk0*128 + seg*4]),       wsrc + (size_t)kk0*VV + seg*4);
    cp16(sptr(&Wt[0][(kk0+4)*128 + seg*4]),   wsrc + (size_t)(kk0+4)*VV + seg*4);
    cp_commit();
    cp16(sptr(&Wt[1][kk0*128 + seg*4]),       wsrc + (size_t)(8 + kk0)*VV + seg*4);
    cp16(sptr(&Wt[1][(kk0+4)*128 + seg*4]),   wsrc + (size_t)(8 + kk0+4)*VV + seg*4);
    cp_commit();

    {   // stage H quarter (rows kq*128 .. +127) with normal loads meanwhile
        const float4* src = (const float4*)g_hT + kq*1024;
        float4* dst = (float4*)Hs;
        #pragma unroll
        for (int i = 0; i < 8; i++) dst[tid + 128*i] = src[tid + 128*i];
    }

    unsigned long long a[4][4];                    // [col][batch-pair]
    #pragma unroll
    for (int c = 0; c < 4; c++)
        #pragma unroll
        for (int i = 0; i < 4; i++) a[c][i] = 0ULL;

    int r_idx = 0, w_idx = 2;                      // rotating buffer indices
    for (int s = 0; s < 16; s++) {
        cp_wait1();                                // stage s landed (s+1 may fly)
        __syncthreads();                           // visible; prior reads of w_idx done
        if (s + 2 < 16) {                          // issue stage s+2
            float* dst = Wt[w_idx];
            cp16(sptr(dst + kk0*128 + seg*4),
                 wsrc + (size_t)((s+2)*8 + kk0)*VV + seg*4);
            cp16(sptr(dst + (kk0+4)*128 + seg*4),
                 wsrc + (size_t)((s+2)*8 + kk0+4)*VV + seg*4);
        }
        cp_commit();

        const float* wbuf = Wt[r_idx];
        #pragma unroll
        for (int kk = 0; kk < 8; kk++) {
            float4 wf = *(const float4*)(wbuf + kk*128 + cl*4);
            unsigned long long w0 = pack2(wf.x, wf.x);
            unsigned long long w1 = pack2(wf.y, wf.y);
            unsigned long long w2 = pack2(wf.z, wf.z);
            unsigned long long w3 = pack2(wf.w, wf.w);
            const ulonglong2* hr = (const ulonglong2*)(Hs + (s*8 + kk)*BB + bq*8);
            ulonglong2 q0 = hr[0], q1 = hr[1];     // broadcast LDS feed 16 FFMA2
            a[0][0]=ffma2(q0.x,w0,a[0][0]); a[0][1]=ffma2(q0.y,w0,a[0][1]);
            a[0][2]=ffma2(q1.x,w0,a[0][2]); a[0][3]=ffma2(q1.y,w0,a[0][3]);
            a[1][0]=ffma2(q0.x,w1,a[1][0]); a[1][1]=ffma2(q0.y,w1,a[1][1]);
            a[1][2]=ffma2(q1.x,w1,a[1][2]); a[1][3]=ffma2(q1.y,w1,a[1][3]);
            a[2][0]=ffma2(q0.x,w2,a[2][0]); a[2][1]=ffma2(q0.y,w2,a[2][1]);
            a[2][2]=ffma2(q1.x,w2,a[2][2]); a[2][3]=ffma2(q1.y,w2,a[2][3]);
            a[3][0]=ffma2(q0.x,w3,a[3][0]); a[3][1]=ffma2(q0.y,w3,a[3][1]);
            a[3][2]=ffma2(q1.x,w3,a[3][2]); a[3][3]=ffma2(q1.y,w3,a[3][3]);
        }
        r_idx = (r_idx == 2) ? 0 : r_idx + 1;
        w_idx = (w_idx == 2) ? 0 : w_idx + 1;
    }

    int v = v0 + cl * 4;
    #pragma unroll
    for (int c = 0; c < 4; c++) {                  // col v+c, batches bq*8..+7
        float2 p0 = unpack2(a[c][0]), p1 = unpack2(a[c][1]);
        float2 p2 = unpack2(a[c][2]), p3 = unpack2(a[c][3]);
        float4* o = (float4*)(g_zl[kq] + (size_t)(v+c)*BB + bq*8);
        o[0] = make_float4(p0.x, p0.y, p1.x, p1.y);
        o[1] = make_float4(p2.x, p2.y, p3.x, p3.y);
    }
}

// ---------- fused exp + partial (exp @ E): grid (250 vchunks, 4 dq), block 128 ----------
__global__ __launch_bounds__(128, 8) void k_emb(const float* __restrict__ E,
                                                const float* __restrict__ bs)
{
    __shared__ __align__(16) float smP[128*BB];    // 16KB: P[128][32]
    __shared__ __align__(16) float Et[3][8*128];   // 12KB: E stage [vv][d-chunk]
    __shared__ float redp[128];
    int tid = threadIdx.x;
    int v0 = blockIdx.x * 128;
    int d0 = blockIdx.y * 128;

    const float* esrc = E + (size_t)v0*DD + d0;
    int kk0 = tid >> 5;
    int seg = tid & 31;

    // prologue: issue E stages 0 and 1 (fly during the exp front)
    cp16(sptr(&Et[0][kk0*128 + seg*4]),     esrc + (size_t)kk0*DD + seg*4);
    cp16(sptr(&Et[0][(kk0+4)*128 + seg*4]), esrc + (size_t)(kk0+4)*DD + seg*4);
    cp_commit();
    cp16(sptr(&Et[1][kk0*128 + seg*4]),     esrc + (size_t)(8 + kk0)*DD + seg*4);
    cp16(sptr(&Et[1][(kk0+4)*128 + seg*4]), esrc + (size_t)(8 + kk0+4)*DD + seg*4);
    cp_commit();

    // ---- exp front
    {   // thread: rows {rr, rr+32, rr+64, rr+96} (local), batches bqf*8..+7
        int rr = tid >> 2, bqf = tid & 3;
        #pragma unroll
        for (int m = 0; m < 4; m++) {
            int lr = rr + m*32;                    // local row 0..127
            int v = v0 + lr;
            float wv[8];
            #pragma unroll
            for (int j = 0; j < 8; j++) wv[j] = 0.f;
            #pragma unroll
            for (int q = 0; q < 4; q++) {
                const float4* p = (const float4*)(g_zl[q] + (size_t)v*BB + bqf*8);
                float4 x = p[0], y = p[1];
                wv[0]+=x.x; wv[1]+=x.y; wv[2]+=x.z; wv[3]+=x.w;
                wv[4]+=y.x; wv[5]+=y.y; wv[6]+=y.z; wv[7]+=y.w;
            }
            float bv = bs[v];
            float4* sp = (float4*)(smP + lr*BB + bqf*8);
            sp[0] = make_float4(expf(wv[0]+bv), expf(wv[1]+bv),
                                expf(wv[2]+bv), expf(wv[3]+bv));
            sp[1] = make_float4(expf(wv[4]+bv), expf(wv[5]+bv),
                                expf(wv[6]+bv), expf(wv[7]+bv));
        }
    }
    __syncthreads();                               // P tile complete

    if ((int)blockIdx.y == (int)(blockIdx.x & 3)) { // psum once per vchunk, spread over dq
        int b2 = tid & 31, sl = tid >> 5;
        float s = 0.f;
        #pragma unroll 4
        for (int u = sl; u < 128; u += 4) s += smP[u*BB + b2];
        redp[sl*32 + b2] = s;
        __syncthreads();
        if (tid < 32)
            g_psum[blockIdx.x*BB + tid] =
                redp[tid] + redp[32+tid] + redp[64+tid] + redp[96+tid];
    }

    // ---- E GEMM mainloop: tid = cl(0..31) + 32*bq(0..3)
    int cl = tid & 31, bq = tid >> 5;
    unsigned long long a[4][4];                    // [d-col][batch-pair]
    #pragma unroll
    for (int c = 0; c < 4; c++)
        #pragma unroll
        for (int i = 0; i < 4; i++) a[c][i] = 0ULL;

    int r_idx = 0, w_idx = 2;
    for (int s = 0; s < 16; s++) {
        cp_wait1();
        __syncthreads();
        if (s + 2 < 16) {
            float* dst = Et[w_idx];
            cp16(sptr(dst + kk0*128 + seg*4),
                 esrc + (size_t)((s+2)*8 + kk0)*DD + seg*4);
            cp16(sptr(dst + (kk0+4)*128 + seg*4),
                 esrc + (size_t)((s+2)*8 + kk0+4)*DD + seg*4);
        }
        cp_commit();

        const float* ebuf = Et[r_idx];
        #pragma unroll
        for (int kk = 0; kk < 8; kk++) {
            float4 ef = *(const float4*)(ebuf + kk*128 + cl*4);
            unsigned long long e0 = pack2(ef.x, ef.x);
            unsigned long long e1 = pack2(ef.y, ef.y);
            unsigned long long e2 = pack2(ef.z, ef.z);
            unsigned long long e3 = pack2(ef.w, ef.w);
            const ulonglong2* wr = (const ulonglong2*)(smP + (s*8 + kk)*BB + bq*8);
            ulonglong2 q0 = wr[0], q1 = wr[1];
            a[0][0]=ffma2(q0.x,e0,a[0][0]); a[0][1]=ffma2(q0.y,e0,a[0][1]);
            a[0][2]=ffma2(q1.x,e0,a[0][2]); a[0][3]=ffma2(q1.y,e0,a[0][3]);
            a[1][0]=ffma2(q0.x,e1,a[1][0]); a[1][1]=ffma2(q0.y,e1,a[1][1]);
            a[1][2]=ffma2(q1.x,e1,a[1][2]); a[1][3]=ffma2(q1.y,e1,a[1][3]);
            a[2][0]=ffma2(q0.x,e2,a[2][0]); a[2][1]=ffma2(q0.y,e2,a[2][1]);
            a[2][2]=ffma2(q1.x,e2,a[2][2]); a[2][3]=ffma2(q1.y,e2,a[2][3]);
            a[3][0]=ffma2(q0.x,e3,a[3][0]); a[3][1]=ffma2(q0.y,e3,a[3][1]);
            a[3][2]=ffma2(q1.x,e3,a[3][2]); a[3][3]=ffma2(q1.y,e3,a[3][3]);
        }
        r_idx = (r_idx == 2) ? 0 : r_idx + 1;
        w_idx = (w_idx == 2) ? 0 : w_idx + 1;
    }

    int d = d0 + cl * 4;
    int pc = blockIdx.x;                   // 0..249 partial chunk
    float* ob = g_acc + ((size_t)pc*BB)*DD + d;
    #pragma unroll
    for (int i = 0; i < 4; i++) {          // rows bq*8+2i, bq*8+2i+1
        float2 t0 = unpack2(a[0][i]), t1 = unpack2(a[1][i]);
        float2 t2 = unpack2(a[2][i]), t3 = unpack2(a[3][i]);
        *(float4*)(ob + (size_t)(bq*8 + 2*i    )*DD) = make_float4(t0.x, t1.x, t2.x, t3.x);
        *(float4*)(ob + (size_t)(bq*8 + 2*i + 1)*DD) = make_float4(t0.y, t1.y, t2.y, t3.y);
    }
}

// ---------- final reduce: normalize soft embedding, write output ----------
// grid (32 b, 8 dgroups), block 256 (8 slices x 32 float2 lanes)
__global__ __launch_bounds__(256) void k_reduce(float* __restrict__ out, int t) {
    __shared__ float2 red[8][32];
    __shared__ float s_inv;
    int b = blockIdx.x, dg = blockIdx.y;
    int tid = threadIdx.x;
    int s = tid >> 5, d2l = tid & 31;

    float2 a = make_float2(0.f, 0.f);
    const float2* gin = (const float2*)g_acc;
    for (int c = s; c < NVB; c += 8) {
        float2 p = gin[((size_t)c*BB + b)*(DD/2) + dg*32 + d2l];
        a.x += p.x; a.y += p.y;
    }
    red[s][d2l] = a;

    if (tid < 32) {                        // deterministic softmax denominator
        float ts = 0.f;
        for (int c = tid; c < NPB; c += 32) ts += g_psum[c*BB + b];
        #pragma unroll
        for (int o = 16; o > 0; o >>= 1) ts += __shfl_xor_sync(0xffffffffu, ts, o);
        if (tid == 0) s_inv = 1.0f / ts;
    }
    __syncthreads();

    if (s == 0) {
        #pragma unroll
        for (int i = 1; i < 8; i++) { a.x += red[i][d2l].x; a.y += red[i][d2l].y; }
        float inv = s_inv;
        a.x *= inv; a.y *= inv;
        int d2 = dg*32 + d2l;
        ((float2*)g_emb)[b*(DD/2) + d2] = a;
        ((float2*)out)[((size_t)b*TT + t)*(DD/2) + d2] = a;
    }
}

extern "C" void kernel_launch(void* const* d_in, const int* in_sizes, int n_in,
                              void* d_out, int out_size) {
    const float* content = (const float*)d_in[0];
    const float* style   = (const float*)d_in[1];
    const float* E       = (const float*)d_in[2];
    const float* Wk      = (const float*)d_in[3];
    const float* Wr      = (const float*)d_in[4];
    const float* bias    = (const float*)d_in[5];
    const float* Ws      = (const float*)d_in[6];
    const float* bs      = (const float*)d_in[7];
    float* out = (float*)d_out;

    k_init<<<BB, DD>>>(E, out);
    k_prep<<<dim3(32, 3), 128>>>(content, style, Wk);   // constant Wk chunks, once
    for (int t = 1; t < TT; t++) {
        int cur = t & 1;
        k_lstm_mm<<<dim3(32, 16), 128>>>(Wk, Wr, cur);
        k_lstm_fin<<<BB, DD>>>(bias, cur);
        k_zl<<<dim3(250, 4), 128>>>(Ws);
        k_emb<<<dim3(250, 4), 128>>>(E, bs);
        k_reduce<<<dim3(BB, 8), 256>>>(out, t);
    }
}